// round 14
// baseline (speedup 1.0000x reference)
#include <cuda_runtime.h>
#include <cuda_fp16.h>
#include <math.h>
#include <stdint.h>

// ---------------------------------------------------------------------------
// GraphSAGE (mean -> max -> lstm aggr -> JK bi-LSTM), N=50000, K=16, C=128.
// Round 14: round-13 (2210us) + gates fused into the recurrent GEMM epilogue
// (gate-interleaved weights, fp16 Z staged in smem, tanh.approx gates).
// ---------------------------------------------------------------------------

#define NN 50000
#define KK 16
#define EE (NN * KK)
#define CC 128
#define JKH 192

#define BM 128
#define BN 128
#define BKT 32
#define RSTRH 40
#define TILE_B (BM * RSTRH * 2)     // 10240
#define STAGE_B (2 * TILE_B)        // 20480
#define SMEM_BYTES (3 * STAGE_B)    // 61440 >= 128*128*2 Z staging

// ---------------- static device scratch -------------------------------------
__device__ int    d_src[EE];
__device__ int    d_is64;
__device__ __half d_xh[NN * CC];
__device__ __half d_aggh[NN * CC];
__device__ __half d_xcath[3 * NN * CC];
__device__ __half d_hAh[NN * CC];
__device__ __half d_hBh[NN * CC];
__device__ float  d_cA[NN * CC];
__device__ __half d_Pa[NN * 512];               // gate-interleaved fp16
__device__ __half d_Pf[3 * NN * 768];
__device__ __half d_Pb[3 * NN * 768];
__device__ __half d_fwdh[3 * NN * JKH];
__device__ __half d_bwdph[3 * NN * JKH];
__device__ float  d_cF[NN * JKH];
__device__ float  d_cB[NN * JKH];
__device__ float  d_w[NN * 3];
__device__ __half d_wh[720896];                 // fp16 weights arena
__device__ float  d_bI[2048];                   // combined interleaved biases

__device__ __forceinline__ float tanh_fast(float x) {
    float y;
    asm("tanh.approx.f32 %0, %1;" : "=f"(y) : "f"(x));
    return y;
}
__device__ __forceinline__ float sigmoid_fast(float x) {
    return fmaf(tanh_fast(0.5f * x), 0.5f, 0.5f);
}

// ---------------- edge-index probe + convert ---------------------------------
__global__ void detect_idx_kernel(const void* ei) {
    const long long* p = (const long long*)ei;
    int lane = threadIdx.x;
    int ok = 1;
#pragma unroll
    for (int i = 0; i < 4; ++i) {
        long long v = p[lane * 4 + i];
        if (v < 0 || v >= NN) ok = 0;
    }
    unsigned m = __ballot_sync(0xffffffffu, ok);
    if (lane == 0) d_is64 = (m == 0xffffffffu) ? 1 : 0;
}

__global__ void convert_src_kernel(const void* ei) {
    int idx = blockIdx.x * blockDim.x + threadIdx.x;
    if (idx >= EE) return;
    if (d_is64) d_src[idx] = (int)((const long long*)ei)[idx];
    else        d_src[idx] = ((const int*)ei)[idx];
}

// ---------------- conversions -------------------------------------------------
__global__ void cvt_half_kernel(const float* __restrict__ in, __half* __restrict__ out, int n4) {
    int i = blockIdx.x * blockDim.x + threadIdx.x;
    if (i >= n4) return;
    float4 v = ((const float4*)in)[i];
    ((__half2*)out)[i * 2]     = __floats2half2_rn(v.x, v.y);
    ((__half2*)out)[i * 2 + 1] = __floats2half2_rn(v.z, v.w);
}

#define NSEG 7
struct CvtJobs {
    const float* src[NSEG];
    __half*      dst[NSEG];
    int          end4[NSEG];
};
__global__ void cvt_half_multi_kernel(CvtJobs jobs, int total4) {
    int i = blockIdx.x * blockDim.x + threadIdx.x;
    if (i >= total4) return;
    int seg = 0;
#pragma unroll
    for (int s = 0; s < NSEG; ++s)
        if (i >= jobs.end4[s]) seg = s + 1;
    int base = (seg == 0) ? 0 : jobs.end4[seg - 1];
    int j = i - base;
    float4 v = ((const float4*)jobs.src[seg])[j];
    ((__half2*)jobs.dst[seg])[j * 2]     = __floats2half2_rn(v.x, v.y);
    ((__half2*)jobs.dst[seg])[j * 2 + 1] = __floats2half2_rn(v.z, v.w);
}

// gate-interleave + fp16: out row (4c+g) = in row (g*H+c); K4 float4s per row
__global__ void permute_cvt_kernel(const float* __restrict__ in, __half* __restrict__ out,
                                   int H, int K4) {
    int idx = blockIdx.x * blockDim.x + threadIdx.x;
    if (idx >= 4 * H * K4) return;
    int r = idx / K4, kq = idx - r * K4;
    int c = r >> 2, g = r & 3;
    float4 v = ((const float4*)in)[(size_t)(g * H + c) * K4 + kq];
    ((__half2*)out)[((size_t)r * K4 + kq) * 2]     = __floats2half2_rn(v.x, v.y);
    ((__half2*)out)[((size_t)r * K4 + kq) * 2 + 1] = __floats2half2_rn(v.z, v.w);
}

__global__ void bias_comb_kernel(const float* __restrict__ bih, const float* __restrict__ bhh,
                                 float* __restrict__ out, int H) {
    int idx = blockIdx.x * blockDim.x + threadIdx.x;
    if (idx >= 4 * H) return;
    int c = idx >> 2, g = idx & 3;
    out[idx] = bih[g * H + c] + bhh[g * H + c];
}

// ---------------- neighbor aggregations (half2) ------------------------------
__global__ void agg_mean_kernel(const __half* __restrict__ X, __half* __restrict__ out) {
    int idx = blockIdx.x * blockDim.x + threadIdx.x;
    if (idx >= NN * 64) return;
    int n = idx >> 6, c2 = idx & 63;
    const int* s = d_src + n * KK;
    float ax = 0.f, ay = 0.f;
#pragma unroll
    for (int j = 0; j < KK; ++j) {
        float2 v = __half22float2(*(const __half2*)(X + (size_t)s[j] * CC + 2 * c2));
        ax += v.x; ay += v.y;
    }
    ((__half2*)out)[idx] = __floats2half2_rn(ax * (1.f / 16.f), ay * (1.f / 16.f));
}

__global__ void agg_max_kernel(const __half* __restrict__ X, __half* __restrict__ out) {
    int idx = blockIdx.x * blockDim.x + threadIdx.x;
    if (idx >= NN * 64) return;
    int n = idx >> 6, c2 = idx & 63;
    const int* s = d_src + n * KK;
    float ax = -INFINITY, ay = -INFINITY;
#pragma unroll
    for (int j = 0; j < KK; ++j) {
        float2 v = __half22float2(*(const __half2*)(X + (size_t)s[j] * CC + 2 * c2));
        ax = fmaxf(ax, v.x); ay = fmaxf(ay, v.y);
    }
    ((__half2*)out)[idx] = __floats2half2_rn(ax, ay);
}

// ---------------- fp16 GEMM (cp.async 3-stage, m16n8k16, ldmatrix) ----------
__global__ __launch_bounds__(256, 2) void h16_gemm_kernel(
    const __half* __restrict__ A, const __half* __restrict__ B2,
    const __half* __restrict__ W1, const __half* __restrict__ W2,
    const float* __restrict__ bias,
    float* __restrict__ CoutF, __half* __restrict__ CoutH,
    int M, int Nc, int K1, int K2, int relu)
{
    extern __shared__ __align__(16) char smraw[];
    const int tid = threadIdx.x, wid = tid >> 5, lane = tid & 31;
    const int grp = lane >> 2, tig = lane & 3;
    const int warpM = wid >> 1, warpN = wid & 1;
    const int rowBase = blockIdx.x * BM, colBase = blockIdx.y * BN;
    const int Ktot = K1 + K2, nk = Ktot / BKT;
    const int cr = tid >> 2;
    const int chh = (tid & 3) * 8;
    const int sub = lane >> 3, r8 = lane & 7;
    uint32_t aoff[2], boff[4];
#pragma unroll
    for (int mt = 0; mt < 2; ++mt)
        aoff[mt] = ((warpM * 32 + mt * 16 + (sub & 1) * 8 + r8) * RSTRH + (sub >> 1) * 8) * 2;
#pragma unroll
    for (int p = 0; p < 4; ++p)
        boff[p] = ((warpN * 64 + (2 * p + (sub >> 1)) * 8 + r8) * RSTRH + (sub & 1) * 8) * 2;
    const uint32_t smBase32 = (uint32_t)__cvta_generic_to_shared(smraw);

    float c[2][8][4];
#pragma unroll
    for (int mt = 0; mt < 2; ++mt)
#pragma unroll
        for (int nt = 0; nt < 8; ++nt)
#pragma unroll
            for (int i = 0; i < 4; ++i) c[mt][nt][i] = 0.f;

    auto issue = [&](int it, int s) {
        if (it < nk) {
            int kk = it * BKT;
            const __half* asrc; const __half* wsrc; int ld, kb;
            if (kk < K1) { asrc = A;  wsrc = W1; ld = K1; kb = kk; }
            else         { asrc = B2; wsrc = W2; ld = K2; kb = kk - K1; }
            char* smA = smraw + s * STAGE_B;
            char* smB = smA + TILE_B;
#pragma unroll
            for (int p = 0; p < 2; ++p) {
                int r = cr + p * 64;
                int row = rowBase + r;
                int rc = (row < M) ? row : 0;
                uint32_t dst = (uint32_t)__cvta_generic_to_shared(smA + r * (RSTRH * 2) + chh * 2);
                const __half* g = asrc + (size_t)rc * ld + kb + chh;
                int sz = (row < M) ? 16 : 0;
                asm volatile("cp.async.cg.shared.global [%0], [%1], 16, %2;\n"
                             :: "r"(dst), "l"(g), "r"(sz));
            }
#pragma unroll
            for (int p = 0; p < 2; ++p) {
                int r = cr + p * 64;
                uint32_t dst = (uint32_t)__cvta_generic_to_shared(smB + r * (RSTRH * 2) + chh * 2);
                const __half* g = wsrc + (size_t)(colBase + r) * ld + kb + chh;
                asm volatile("cp.async.cg.shared.global [%0], [%1], 16;\n"
                             :: "r"(dst), "l"(g));
            }
        }
        asm volatile("cp.async.commit_group;\n");
    };

    issue(0, 0);
    issue(1, 1);
    for (int it = 0; it < nk; ++it) {
        asm volatile("cp.async.wait_group 1;\n");
        __syncthreads();
        const int s = it % 3;
        const uint32_t smA32 = smBase32 + s * STAGE_B;
        const uint32_t smB32 = smA32 + TILE_B;
#pragma unroll
        for (int kt = 0; kt < 2; ++kt) {
            const uint32_t kbyte = kt * 32;
            uint32_t af[2][4], bf[8][2];
#pragma unroll
            for (int mt = 0; mt < 2; ++mt)
                asm volatile("ldmatrix.sync.aligned.m8n8.x4.shared.b16 {%0,%1,%2,%3}, [%4];\n"
                             : "=r"(af[mt][0]), "=r"(af[mt][1]), "=r"(af[mt][2]), "=r"(af[mt][3])
                             : "r"(smA32 + aoff[mt] + kbyte));
#pragma unroll
            for (int p = 0; p < 4; ++p)
                asm volatile("ldmatrix.sync.aligned.m8n8.x4.shared.b16 {%0,%1,%2,%3}, [%4];\n"
                             : "=r"(bf[2 * p][0]), "=r"(bf[2 * p][1]),
                               "=r"(bf[2 * p + 1][0]), "=r"(bf[2 * p + 1][1])
                             : "r"(smB32 + boff[p] + kbyte));
#pragma unroll
            for (int mt = 0; mt < 2; ++mt)
#pragma unroll
                for (int nt = 0; nt < 8; ++nt)
                    asm volatile("mma.sync.aligned.m16n8k16.row.col.f32.f16.f16.f32 "
                                 "{%0,%1,%2,%3}, {%4,%5,%6,%7}, {%8,%9}, {%0,%1,%2,%3};\n"
                                 : "+f"(c[mt][nt][0]), "+f"(c[mt][nt][1]),
                                   "+f"(c[mt][nt][2]), "+f"(c[mt][nt][3])
                                 : "r"(af[mt][0]), "r"(af[mt][1]), "r"(af[mt][2]), "r"(af[mt][3]),
                                   "r"(bf[nt][0]), "r"(bf[nt][1]));
        }
        issue(it + 2, (it + 2) % 3);
    }

#pragma unroll
    for (int mt = 0; mt < 2; ++mt) {
#pragma unroll
        for (int nt = 0; nt < 8; ++nt) {
            int col = colBase + warpN * 64 + nt * 8 + tig * 2;
            float b0 = bias ? bias[col] : 0.f;
            float b1 = bias ? bias[col + 1] : 0.f;
            int r0 = rowBase + warpM * 32 + mt * 16 + grp;
            int r1 = r0 + 8;
            float v0 = c[mt][nt][0] + b0, v1 = c[mt][nt][1] + b1;
            float v2 = c[mt][nt][2] + b0, v3 = c[mt][nt][3] + b1;
            if (relu) { v0 = fmaxf(v0, 0.f); v1 = fmaxf(v1, 0.f);
                        v2 = fmaxf(v2, 0.f); v3 = fmaxf(v3, 0.f); }
            if (CoutF) {
                if (r0 < M) *(float2*)(CoutF + (size_t)r0 * Nc + col) = make_float2(v0, v1);
                if (r1 < M) *(float2*)(CoutF + (size_t)r1 * Nc + col) = make_float2(v2, v3);
            } else {
                if (r0 < M) *(__half2*)(CoutH + (size_t)r0 * Nc + col) = __floats2half2_rn(v0, v1);
                if (r1 < M) *(__half2*)(CoutH + (size_t)r1 * Nc + col) = __floats2half2_rn(v2, v3);
            }
        }
    }
}

// ---------------- fused recurrent step: Z = A@W^T (interleaved), gates -------
__global__ __launch_bounds__(256, 2) void fused_step_kernel(
    const __half* __restrict__ A, const __half* __restrict__ W,
    const __half* __restrict__ P, const float* __restrict__ bI,
    const int* __restrict__ src, int t,
    float* __restrict__ c_st, __half* __restrict__ h_out,
    int M, int fourH, int K1)
{
    extern __shared__ __align__(16) char smraw[];
    const int tid = threadIdx.x, wid = tid >> 5, lane = tid & 31;
    const int grp = lane >> 2, tig = lane & 3;
    const int warpM = wid >> 1, warpN = wid & 1;
    const int rowBase = blockIdx.x * BM, colBase = blockIdx.y * BN;
    const int nk = K1 / BKT;
    const int cr = tid >> 2;
    const int chh = (tid & 3) * 8;
    const int sub = lane >> 3, r8 = lane & 7;
    uint32_t aoff[2], boff[4];
#pragma unroll
    for (int mt = 0; mt < 2; ++mt)
        aoff[mt] = ((warpM * 32 + mt * 16 + (sub & 1) * 8 + r8) * RSTRH + (sub >> 1) * 8) * 2;
#pragma unroll
    for (int p = 0; p < 4; ++p)
        boff[p] = ((warpN * 64 + (2 * p + (sub >> 1)) * 8 + r8) * RSTRH + (sub & 1) * 8) * 2;
    const uint32_t smBase32 = (uint32_t)__cvta_generic_to_shared(smraw);

    float c[2][8][4];
#pragma unroll
    for (int mt = 0; mt < 2; ++mt)
#pragma unroll
        for (int nt = 0; nt < 8; ++nt)
#pragma unroll
            for (int i = 0; i < 4; ++i) c[mt][nt][i] = 0.f;

    auto issue = [&](int it, int s) {
        if (it < nk) {
            int kb = it * BKT;
            char* smA = smraw + s * STAGE_B;
            char* smB = smA + TILE_B;
#pragma unroll
            for (int p = 0; p < 2; ++p) {
                int r = cr + p * 64;
                int row = rowBase + r;
                int rc = (row < M) ? row : 0;
                uint32_t dst = (uint32_t)__cvta_generic_to_shared(smA + r * (RSTRH * 2) + chh * 2);
                const __half* g = A + (size_t)rc * K1 + kb + chh;
                int sz = (row < M) ? 16 : 0;
                asm volatile("cp.async.cg.shared.global [%0], [%1], 16, %2;\n"
                             :: "r"(dst), "l"(g), "r"(sz));
            }
#pragma unroll
            for (int p = 0; p < 2; ++p) {
                int r = cr + p * 64;
                uint32_t dst = (uint32_t)__cvta_generic_to_shared(smB + r * (RSTRH * 2) + chh * 2);
                const __half* g = W + (size_t)(colBase + r) * K1 + kb + chh;
                asm volatile("cp.async.cg.shared.global [%0], [%1], 16;\n"
                             :: "r"(dst), "l"(g));
            }
        }
        asm volatile("cp.async.commit_group;\n");
    };

    issue(0, 0);
    issue(1, 1);
    for (int it = 0; it < nk; ++it) {
        asm volatile("cp.async.wait_group 1;\n");
        __syncthreads();
        const int s = it % 3;
        const uint32_t smA32 = smBase32 + s * STAGE_B;
        const uint32_t smB32 = smA32 + TILE_B;
#pragma unroll
        for (int kt = 0; kt < 2; ++kt) {
            const uint32_t kbyte = kt * 32;
            uint32_t af[2][4], bf[8][2];
#pragma unroll
            for (int mt = 0; mt < 2; ++mt)
                asm volatile("ldmatrix.sync.aligned.m8n8.x4.shared.b16 {%0,%1,%2,%3}, [%4];\n"
                             : "=r"(af[mt][0]), "=r"(af[mt][1]), "=r"(af[mt][2]), "=r"(af[mt][3])
                             : "r"(smA32 + aoff[mt] + kbyte));
#pragma unroll
            for (int p = 0; p < 4; ++p)
                asm volatile("ldmatrix.sync.aligned.m8n8.x4.shared.b16 {%0,%1,%2,%3}, [%4];\n"
                             : "=r"(bf[2 * p][0]), "=r"(bf[2 * p][1]),
                               "=r"(bf[2 * p + 1][0]), "=r"(bf[2 * p + 1][1])
                             : "r"(smB32 + boff[p] + kbyte));
#pragma unroll
            for (int mt = 0; mt < 2; ++mt)
#pragma unroll
                for (int nt = 0; nt < 8; ++nt)
                    asm volatile("mma.sync.aligned.m16n8k16.row.col.f32.f16.f16.f32 "
                                 "{%0,%1,%2,%3}, {%4,%5,%6,%7}, {%8,%9}, {%0,%1,%2,%3};\n"
                                 : "+f"(c[mt][nt][0]), "+f"(c[mt][nt][1]),
                                   "+f"(c[mt][nt][2]), "+f"(c[mt][nt][3])
                                 : "r"(af[mt][0]), "r"(af[mt][1]), "r"(af[mt][2]), "r"(af[mt][3]),
                                   "r"(bf[nt][0]), "r"(bf[nt][1]));
        }
        issue(it + 2, (it + 2) % 3);
    }

    // ---- epilogue: stage Z (fp16, same rounding as old gmem store) in smem
    asm volatile("cp.async.wait_group 0;\n");
    __syncthreads();
    __half* Zs = (__half*)smraw;            // 128 x 128 fp16 = 32 KB
#pragma unroll
    for (int mt = 0; mt < 2; ++mt)
#pragma unroll
        for (int nt = 0; nt < 8; ++nt) {
            int col = warpN * 64 + nt * 8 + tig * 2;
            int r0 = warpM * 32 + mt * 16 + grp;
            *(__half2*)&Zs[r0 * BN + col]       = __floats2half2_rn(c[mt][nt][0], c[mt][nt][1]);
            *(__half2*)&Zs[(r0 + 8) * BN + col] = __floats2half2_rn(c[mt][nt][2], c[mt][nt][3]);
        }
    __syncthreads();

    const int H = fourH >> 2;
    const int cl = tid & 31;                       // fixed channel per thread
    const int chan = (colBase >> 2) + cl;          // global channel index
    float4 bb = *(const float4*)(bI + colBase + 4 * cl);
#pragma unroll
    for (int i = 0; i < 16; ++i) {
        int r = (tid >> 5) + i * 8;
        int n = rowBase + r;
        if (n >= M) continue;
        int pn = src ? src[n * KK + t] : n;
        uint2 zu = *(const uint2*)&Zs[r * BN + 4 * cl];
        float2 za = __half22float2(*(const __half2*)&zu.x);
        float2 zb = __half22float2(*(const __half2*)&zu.y);
        uint2 pu = *(const uint2*)(P + (size_t)pn * fourH + colBase + 4 * cl);
        float2 pa = __half22float2(*(const __half2*)&pu.x);
        float2 pb = __half22float2(*(const __half2*)&pu.y);
        float zi = za.x + pa.x + bb.x;
        float zf = za.y + pa.y + bb.y;
        float zg = zb.x + pb.x + bb.z;
        float zo = zb.y + pb.y + bb.w;
        float ig = sigmoid_fast(zi), fg = sigmoid_fast(zf);
        float gg = tanh_fast(zg),    og = sigmoid_fast(zo);
        size_t ci = (size_t)n * H + chan;
        float cn = fg * c_st[ci] + ig * gg;
        c_st[ci] = cn;
        h_out[ci] = __float2half_rn(og * tanh_fast(cn));
    }
}

// ---------------- first-step gates (interleaved P, h0=c0=0) ------------------
__global__ void gates_first_kernel(
    const __half* __restrict__ P, const float* __restrict__ bI,
    const int* __restrict__ src, int t,
    float* __restrict__ c_st, __half* __restrict__ h_out, int H)
{
    int idx = blockIdx.x * blockDim.x + threadIdx.x;
    if (idx >= NN * H) return;
    int n = idx / H, cl = idx - n * H;
    int pn = src ? src[n * KK + t] : n;
    uint2 pu = *(const uint2*)(P + (size_t)pn * 4 * H + 4 * cl);
    float2 pa = __half22float2(*(const __half2*)&pu.x);
    float2 pb = __half22float2(*(const __half2*)&pu.y);
    float4 b = *(const float4*)(bI + 4 * cl);
    float ig = sigmoid_fast(pa.x + b.x);
    float gg = tanh_fast(pb.x + b.z);
    float og = sigmoid_fast(pb.y + b.w);
    float cn = ig * gg;
    c_st[idx] = cn;
    h_out[idx] = __float2half_rn(og * tanh_fast(cn));
}

// ---------------- JK attention scores + softmax (precise math) ---------------
__global__ void jk_score_kernel(const float* __restrict__ attw,
                                const float* __restrict__ attb,
                                float* __restrict__ wout)
{
    int gtid = blockIdx.x * blockDim.x + threadIdx.x;
    int node = gtid >> 5;
    int lane = gtid & 31;
    if (node >= NN) return;
    float sc[3];
#pragma unroll
    for (int t = 0; t < 3; ++t) {
        const __half* f = d_fwdh  + (size_t)t * NN * JKH + (size_t)node * JKH;
        const __half* b = d_bwdph + (size_t)t * NN * JKH + (size_t)node * JKH;
        float s = 0.f;
        for (int k = lane; k < JKH; k += 32)
            s += __half2float(f[k]) * attw[k] + __half2float(b[k]) * attw[JKH + k];
#pragma unroll
        for (int off = 16; off > 0; off >>= 1)
            s += __shfl_xor_sync(0xffffffffu, s, off);
        sc[t] = s + attb[0];
    }
    if (lane == 0) {
        float m = fmaxf(sc[0], fmaxf(sc[1], sc[2]));
        float e0 = expf(sc[0] - m), e1 = expf(sc[1] - m), e2 = expf(sc[2] - m);
        float inv = 1.f / (e0 + e1 + e2);
        wout[node * 3 + 0] = e0 * inv;
        wout[node * 3 + 1] = e1 * inv;
        wout[node * 3 + 2] = e2 * inv;
    }
}

__global__ void jk_combine_kernel(float* __restrict__ out) {
    int idx = blockIdx.x * blockDim.x + threadIdx.x;
    if (idx >= NN * 64) return;
    int n = idx >> 6;
    float w0 = d_w[n * 3 + 0], w1 = d_w[n * 3 + 1], w2 = d_w[n * 3 + 2];
    float2 a = __half22float2(((const __half2*)d_xcath)[idx]);
    float2 b = __half22float2(((const __half2*)(d_xcath + NN * CC))[idx]);
    float2 c = __half22float2(((const __half2*)(d_xcath + 2 * NN * CC))[idx]);
    ((float2*)out)[idx] = make_float2(w0 * a.x + w1 * b.x + w2 * c.x,
                                      w0 * a.y + w1 * b.y + w2 * c.y);
}

// ---------------------------------------------------------------------------
static inline int cdiv(int a, int b) { return (a + b - 1) / b; }

extern "C" void kernel_launch(void* const* d_in, const int* in_sizes, int n_in,
                              void* d_out, int out_size)
{
    const void* ei = nullptr;
    const float* x = nullptr;
    const float* wp[23];
    int wcount = 0;
    for (int i = 0; i < n_in; ++i) {
        if (in_sizes[i] == 2 * EE)       ei = d_in[i];
        else if (in_sizes[i] == NN * CC) x  = (const float*)d_in[i];
        else if (wcount < 23)            wp[wcount++] = (const float*)d_in[i];
    }
    const float *Wl1 = wp[0],  *bl1 = wp[1],  *Wr1 = wp[2];
    const float *Wl2 = wp[3],  *bl2 = wp[4],  *Wr2 = wp[5];
    const float *Wl3 = wp[6],  *bl3 = wp[7],  *Wr3 = wp[8];
    const float *Wih_a = wp[9],  *Whh_a = wp[10], *bih_a = wp[11], *bhh_a = wp[12];
    const float *Wih_f = wp[13], *Whh_f = wp[14], *bih_f = wp[15], *bhh_f = wp[16];
    const float *Wih_b = wp[17], *Whh_b = wp[18], *bih_b = wp[19], *bhh_b = wp[20];
    const float *att_w = wp[21], *att_b = wp[22];

    __half *xh, *aggh, *xcath, *hAh, *hBh, *fwdh, *bwdph, *wh, *Pa, *Pf, *Pb;
    float *cA, *cF, *cB, *wbuf, *bI;
    int* srcp;
    cudaGetSymbolAddress((void**)&srcp,  d_src);
    cudaGetSymbolAddress((void**)&xh,    d_xh);
    cudaGetSymbolAddress((void**)&aggh,  d_aggh);
    cudaGetSymbolAddress((void**)&xcath, d_xcath);
    cudaGetSymbolAddress((void**)&hAh,   d_hAh);
    cudaGetSymbolAddress((void**)&hBh,   d_hBh);
    cudaGetSymbolAddress((void**)&cA,    d_cA);
    cudaGetSymbolAddress((void**)&Pa,    d_Pa);
    cudaGetSymbolAddress((void**)&Pf,    d_Pf);
    cudaGetSymbolAddress((void**)&Pb,    d_Pb);
    cudaGetSymbolAddress((void**)&fwdh,  d_fwdh);
    cudaGetSymbolAddress((void**)&bwdph, d_bwdph);
    cudaGetSymbolAddress((void**)&cF,    d_cF);
    cudaGetSymbolAddress((void**)&cB,    d_cB);
    cudaGetSymbolAddress((void**)&wbuf,  d_w);
    cudaGetSymbolAddress((void**)&wh,    d_wh);
    cudaGetSymbolAddress((void**)&bI,    d_bI);

    __half* hWl1 = wh;                 __half* hWr1 = hWl1 + 16384;
    __half* hWl2 = hWr1 + 16384;       __half* hWr2 = hWl2 + 16384;
    __half* hWl3 = hWr2 + 16384;       __half* hWr3 = hWl3 + 16384;
    __half* hWih_a = hWr3 + 16384;     __half* hWhh_a = hWih_a + 65536;   // interleaved
    __half* hWih_f = hWhh_a + 65536;   __half* hWhh_f = hWih_f + 98304;
    __half* hWih_b = hWhh_f + 147456;  __half* hWhh_b = hWih_b + 98304;
    float* bIa = bI;        // 512
    float* bIf = bI + 512;  // 768
    float* bIb = bI + 1280; // 768

    __half* h1h = xcath;
    __half* h2h = xcath + NN * CC;
    __half* h3h = xcath + 2 * NN * CC;
    float* out = (float*)d_out;

    cudaFuncSetAttribute(h16_gemm_kernel,
                         cudaFuncAttributeMaxDynamicSharedMemorySize, SMEM_BYTES);
    cudaFuncSetAttribute(fused_step_kernel,
                         cudaFuncAttributeMaxDynamicSharedMemorySize, SMEM_BYTES);

    const int NH2_BLK = cdiv(NN * 64, 256);
    dim3 g128(cdiv(NN, BM), 1);
    dim3 g512(cdiv(NN, BM), 4);
    dim3 g768(cdiv(NN, BM), 6);
    dim3 g768x3(cdiv(3 * NN, BM), 6);

    // ---- prep
    detect_idx_kernel<<<1, 32>>>(ei);
    convert_src_kernel<<<cdiv(EE, 256), 256>>>(ei);
    cvt_half_kernel<<<cdiv(NN * CC / 4, 256), 256>>>(x, xh, NN * CC / 4);
    {
        CvtJobs jobs;
        const float* srcs[NSEG] = {Wl1, Wr1, Wl2, Wr2, Wl3, Wr3, nullptr};
        __half* dsts[NSEG] = {hWl1, hWr1, hWl2, hWr2, hWl3, hWr3, nullptr};
        int n4s[NSEG] = {4096, 4096, 4096, 4096, 4096, 4096, 0};
        int acc = 0;
        for (int s = 0; s < NSEG; ++s) {
            jobs.src[s] = srcs[s] ? srcs[s] : Wl1;
            jobs.dst[s] = dsts[s] ? dsts[s] : hWl1;
            acc += n4s[s];
            jobs.end4[s] = acc;
        }
        cvt_half_multi_kernel<<<cdiv(acc, 256), 256>>>(jobs, acc);
    }
    permute_cvt_kernel<<<64, 256>>>(Wih_a, hWih_a, 128, 32);
    permute_cvt_kernel<<<64, 256>>>(Whh_a, hWhh_a, 128, 32);
    permute_cvt_kernel<<<96, 256>>>(Wih_f, hWih_f, 192, 32);
    permute_cvt_kernel<<<144, 256>>>(Whh_f, hWhh_f, 192, 48);
    permute_cvt_kernel<<<96, 256>>>(Wih_b, hWih_b, 192, 32);
    permute_cvt_kernel<<<144, 256>>>(Whh_b, hWhh_b, 192, 48);
    bias_comb_kernel<<<2, 256>>>(bih_a, bhh_a, bIa, 128);
    bias_comb_kernel<<<3, 256>>>(bih_f, bhh_f, bIf, 192);
    bias_comb_kernel<<<3, 256>>>(bih_b, bhh_b, bIb, 192);

    // ---- layer 1: mean SAGE + relu -> h1 (fp16)
    agg_mean_kernel<<<NH2_BLK, 256>>>(xh, aggh);
    h16_gemm_kernel<<<g128, 256, SMEM_BYTES>>>(aggh, xh, hWl1, hWr1, bl1,
                                               nullptr, h1h, NN, 128, 128, 128, 1);

    // ---- layer 2: max SAGE + relu -> h2 (fp16)
    agg_max_kernel<<<NH2_BLK, 256>>>(h1h, aggh);
    h16_gemm_kernel<<<g128, 256, SMEM_BYTES>>>(aggh, h1h, hWl2, hWr2, bl2,
                                               nullptr, h2h, NN, 128, 128, 128, 1);

    // ---- layer 3: LSTM aggregation (interleaved P, fused steps)
    h16_gemm_kernel<<<g512, 256, SMEM_BYTES>>>(h2h, nullptr, hWih_a, nullptr, nullptr,
                                               nullptr, Pa, NN, 512, 128, 0, 0);
    gates_first_kernel<<<cdiv(NN * CC, 256), 256>>>(Pa, bIa, srcp, 0, cA, hAh, 128);
    __half* hcur = hAh;
    __half* hnxt = hBh;
    for (int t = 1; t < KK; ++t) {
        fused_step_kernel<<<g512, 256, SMEM_BYTES>>>(hcur, hWhh_a, Pa, bIa, srcp, t,
                                                     cA, hnxt, NN, 512, 128);
        __half* tmp = hcur; hcur = hnxt; hnxt = tmp;
    }
    h16_gemm_kernel<<<g128, 256, SMEM_BYTES>>>(hcur, h2h, hWl3, hWr3, bl3,
                                               nullptr, h3h, NN, 128, 128, 128, 0);

    // ---- JK bi-LSTM (interleaved P, fused steps)
    h16_gemm_kernel<<<g768x3, 256, SMEM_BYTES>>>(xcath, nullptr, hWih_f, nullptr, nullptr,
                                                 nullptr, Pf, 3 * NN, 768, 128, 0, 0);
    h16_gemm_kernel<<<g768x3, 256, SMEM_BYTES>>>(xcath, nullptr, hWih_b, nullptr, nullptr,
                                                 nullptr, Pb, 3 * NN, 768, 128, 0, 0);

    gates_first_kernel<<<cdiv(NN * JKH, 256), 256>>>(Pf, bIf, nullptr, 0, cF, fwdh, JKH);
    gates_first_kernel<<<cdiv(NN * JKH, 256), 256>>>(Pb + (size_t)2 * NN * 768, bIb,
                                                     nullptr, 0, cB,
                                                     bwdph + (size_t)2 * NN * JKH, JKH);
    for (int t = 1; t < 3; ++t) {
        fused_step_kernel<<<g768, 256, SMEM_BYTES>>>(
            fwdh + (size_t)(t - 1) * NN * JKH, hWhh_f,
            Pf + (size_t)t * NN * 768, bIf, nullptr, 0,
            cF, fwdh + (size_t)t * NN * JKH, NN, 768, 192);
        fused_step_kernel<<<g768, 256, SMEM_BYTES>>>(
            bwdph + (size_t)(3 - t) * NN * JKH, hWhh_b,
            Pb + (size_t)(2 - t) * NN * 768, bIb, nullptr, 0,
            cB, bwdph + (size_t)(2 - t) * NN * JKH, NN, 768, 192);
    }

    // ---- attention + combine
    jk_score_kernel<<<cdiv(NN * 32, 256), 256>>>(att_w, att_b, wbuf);
    jk_combine_kernel<<<NH2_BLK, 256>>>(out);

    (void)out_size;
}